// round 1
// baseline (speedup 1.0000x reference)
#include <cuda_runtime.h>
#include <math_constants.h>

// Scratch for segment offsets (allocation-free rule: __device__ global).
// Sized generously in case of shape variants (up to 64K segments).
__device__ int g_offsets[65537];

// ---------------------------------------------------------------------------
// Kernel 1: compute per-segment start offsets via binary search on the sorted
// segment_ids array. Handles both int64 (as the reference requests) and int32
// (what JAX actually produces without x64) via on-device dtype sniffing.
// ---------------------------------------------------------------------------
__global__ void seg_offsets_kernel(const void* __restrict__ seg, int n, int G) {
    int g = blockIdx.x * blockDim.x + threadIdx.x;
    if (g > G) return;

    // dtype sniff: int64 word at index n/4 covers int32 elements n/2, n/2+1.
    // Sorted ids: middle element ~G/2 != 0, so int32 data read as int64 is
    // >= 2^32; genuine int64 data is a small id.
    const long long probe = ((const long long*)seg)[n >> 2];
    const bool is64 = (probe >= 0) && (probe < (1LL << 31));

    // lower_bound: first index i with seg[i] >= g
    int lo = 0, hi = n;
    if (is64) {
        const long long* s = (const long long*)seg;
        const long long gv = (long long)g;
        while (lo < hi) {
            int mid = (lo + hi) >> 1;
            if (s[mid] < gv) lo = mid + 1; else hi = mid;
        }
    } else {
        const int* s = (const int*)seg;
        while (lo < hi) {
            int mid = (lo + hi) >> 1;
            if (s[mid] < g) lo = mid + 1; else hi = mid;
        }
    }
    g_offsets[g] = lo;
}

// ---------------------------------------------------------------------------
// Kernel 2: one block per segment. 128 threads = 4 row-groups x 32 lanes.
// Lane l owns features [4l, 4l+4) via float4 (coalesced LDG.128).
// Row-group r processes rows start+r, start+r+4, ...
// Cross-group combine in shared memory, then thread f writes the 4 stats.
// ---------------------------------------------------------------------------
__global__ void __launch_bounds__(128, 8)
seg_pool_kernel(const float* __restrict__ x, float* __restrict__ out, int G) {
    const int g = blockIdx.x;
    const int start = g_offsets[g];
    const int end   = g_offsets[g + 1];

    const int lane = threadIdx.x & 31;
    const int grp  = threadIdx.x >> 5;

    float4 s  = make_float4(0.f, 0.f, 0.f, 0.f);
    float4 q  = make_float4(0.f, 0.f, 0.f, 0.f);
    float4 mx = make_float4(-CUDART_INF_F, -CUDART_INF_F, -CUDART_INF_F, -CUDART_INF_F);
    float4 mn = make_float4( CUDART_INF_F,  CUDART_INF_F,  CUDART_INF_F,  CUDART_INF_F);

    const float4* __restrict__ xv = (const float4*)x;  // row stride = 32 float4

    #pragma unroll 4
    for (int r = start + grp; r < end; r += 4) {
        float4 v = __ldg(&xv[(size_t)r * 32 + lane]);
        s.x += v.x; s.y += v.y; s.z += v.z; s.w += v.w;
        q.x = fmaf(v.x, v.x, q.x); q.y = fmaf(v.y, v.y, q.y);
        q.z = fmaf(v.z, v.z, q.z); q.w = fmaf(v.w, v.w, q.w);
        mx.x = fmaxf(mx.x, v.x); mx.y = fmaxf(mx.y, v.y);
        mx.z = fmaxf(mx.z, v.z); mx.w = fmaxf(mx.w, v.w);
        mn.x = fminf(mn.x, v.x); mn.y = fminf(mn.y, v.y);
        mn.z = fminf(mn.z, v.z); mn.w = fminf(mn.w, v.w);
    }

    // partials: [stat][group][lane] as float4 -> 4*4*32*16B = 8 KB
    __shared__ float4 sm4[4][4][32];
    sm4[0][grp][lane] = s;
    sm4[1][grp][lane] = q;
    sm4[2][grp][lane] = mx;
    sm4[3][grp][lane] = mn;
    __syncthreads();

    // thread f in [0,128) combines the 4 group partials for feature f
    const int f = threadIdx.x;
    float sum = 0.f, sq = 0.f;
    float M = -CUDART_INF_F, m = CUDART_INF_F;
    #pragma unroll
    for (int k = 0; k < 4; k++) {
        const float* p0 = (const float*)&sm4[0][k][0];
        const float* p1 = (const float*)&sm4[1][k][0];
        const float* p2 = (const float*)&sm4[2][k][0];
        const float* p3 = (const float*)&sm4[3][k][0];
        sum += p0[f];
        sq  += p1[f];
        M = fmaxf(M, p2[f]);
        m = fminf(m, p3[f]);
    }

    const float cnt  = (float)(end - start);
    const float mean = sum / cnt;
    const float var  = (sq - cnt * mean * mean) / (cnt - 1.0f);
    const float sd   = sqrtf(fmaxf(var, 0.0f));

    float* o = out + (size_t)g * 512;  // [4][128] per segment
    o[f]        = M;
    o[128 + f]  = m;
    o[256 + f]  = mean;
    o[384 + f]  = sd;
}

extern "C" void kernel_launch(void* const* d_in, const int* in_sizes, int n_in,
                              void* d_out, int out_size) {
    const float* x   = (const float*)d_in[0];
    const void*  seg = d_in[1];
    float* out = (float*)d_out;

    const int D = 128;
    const int n = in_sizes[0] / D;          // number of rows
    const int G = out_size / (4 * D);       // number of segments

    int tb = 256;
    int nb = (G + 1 + tb - 1) / tb;
    seg_offsets_kernel<<<nb, tb>>>(seg, n, G);
    seg_pool_kernel<<<G, 128>>>(x, out, G);
}

// round 2
// speedup vs baseline: 1.1213x; 1.1213x over previous
#include <cuda_runtime.h>
#include <math_constants.h>

// Scratch for segment offsets (allocation-free rule: __device__ global).
__device__ int g_offsets[65537];

// ---------------------------------------------------------------------------
// Kernel 1: streaming boundary scan over the SORTED segment_ids array.
// Thread i reads seg[i] and seg[i+1]; at each transition it fills the
// offsets for every id in (seg[i], seg[i+1]]. Edge threads fill the head
// ([0, seg[0]]) and tail ((seg[n-1], G]). One coalesced pass (~2us) instead
// of 16K dependent-load binary searches.
// Handles both int64 (reference dtype) and int32 (JAX default) via sniffing.
// ---------------------------------------------------------------------------
__global__ void seg_boundaries_kernel(const void* __restrict__ seg, int n, int G) {
    const int i = blockIdx.x * blockDim.x + threadIdx.x;
    if (i >= n) return;

    // dtype sniff: int64 word at index n/4 covers int32 elements n/2, n/2+1.
    // Sorted ids: middle element ~G/2 != 0, so int32 data read as int64 is
    // >= 2^32; genuine int64 data stays a small id.
    const long long probe = ((const long long*)seg)[n >> 2];
    const bool is64 = (probe >= 0) && (probe < (1LL << 31));

    int id, next;
    if (is64) {
        const long long* s = (const long long*)seg;
        id   = (int)s[i];
        next = (i + 1 < n) ? (int)s[i + 1] : G;
    } else {
        const int* s = (const int*)seg;
        id   = s[i];
        next = (i + 1 < n) ? s[i + 1] : G;
    }

    if (i == 0) {
        for (int g = 0; g <= id; g++) g_offsets[g] = 0;
    }
    // first row of every segment in (id, next] is i+1
    for (int g = id + 1; g <= next; g++) g_offsets[g] = i + 1;
}

// ---------------------------------------------------------------------------
// Kernel 2: one block per segment. 128 threads = 4 row-groups x 32 lanes.
// Lane l owns features [4l, 4l+4) via float4 (coalesced LDG.128 streaming).
// Row-group r processes rows start+r, start+r+4, ...
// Cross-group combine in shared memory, then thread f writes the 4 stats.
// ---------------------------------------------------------------------------
__global__ void __launch_bounds__(128, 12)
seg_pool_kernel(const float* __restrict__ x, float* __restrict__ out, int G) {
    const int g = blockIdx.x;
    const int start = g_offsets[g];
    const int end   = g_offsets[g + 1];

    const int lane = threadIdx.x & 31;
    const int grp  = threadIdx.x >> 5;

    float4 s  = make_float4(0.f, 0.f, 0.f, 0.f);
    float4 q  = make_float4(0.f, 0.f, 0.f, 0.f);
    float4 mx = make_float4(-CUDART_INF_F, -CUDART_INF_F, -CUDART_INF_F, -CUDART_INF_F);
    float4 mn = make_float4( CUDART_INF_F,  CUDART_INF_F,  CUDART_INF_F,  CUDART_INF_F);

    const float4* __restrict__ xv = (const float4*)x;  // row stride = 32 float4

    #pragma unroll 4
    for (int r = start + grp; r < end; r += 4) {
        float4 v = __ldcs(&xv[(size_t)r * 32 + lane]);
        s.x += v.x; s.y += v.y; s.z += v.z; s.w += v.w;
        q.x = fmaf(v.x, v.x, q.x); q.y = fmaf(v.y, v.y, q.y);
        q.z = fmaf(v.z, v.z, q.z); q.w = fmaf(v.w, v.w, q.w);
        mx.x = fmaxf(mx.x, v.x); mx.y = fmaxf(mx.y, v.y);
        mx.z = fmaxf(mx.z, v.z); mx.w = fmaxf(mx.w, v.w);
        mn.x = fminf(mn.x, v.x); mn.y = fminf(mn.y, v.y);
        mn.z = fminf(mn.z, v.z); mn.w = fminf(mn.w, v.w);
    }

    // partials: [stat][group][lane] as float4 -> 4*4*32*16B = 8 KB
    __shared__ float4 sm4[4][4][32];
    sm4[0][grp][lane] = s;
    sm4[1][grp][lane] = q;
    sm4[2][grp][lane] = mx;
    sm4[3][grp][lane] = mn;
    __syncthreads();

    // thread f in [0,128) combines the 4 group partials for feature f
    const int f = threadIdx.x;
    float sum = 0.f, sq = 0.f;
    float M = -CUDART_INF_F, m = CUDART_INF_F;
    #pragma unroll
    for (int k = 0; k < 4; k++) {
        const float* p0 = (const float*)&sm4[0][k][0];
        const float* p1 = (const float*)&sm4[1][k][0];
        const float* p2 = (const float*)&sm4[2][k][0];
        const float* p3 = (const float*)&sm4[3][k][0];
        sum += p0[f];
        sq  += p1[f];
        M = fmaxf(M, p2[f]);
        m = fminf(m, p3[f]);
    }

    const float cnt  = (float)(end - start);
    const float mean = sum / cnt;
    const float var  = (sq - cnt * mean * mean) / (cnt - 1.0f);
    const float sd   = sqrtf(fmaxf(var, 0.0f));

    float* o = out + (size_t)g * 512;  // [4][128] per segment
    o[f]        = M;
    o[128 + f]  = m;
    o[256 + f]  = mean;
    o[384 + f]  = sd;
}

extern "C" void kernel_launch(void* const* d_in, const int* in_sizes, int n_in,
                              void* d_out, int out_size) {
    const float* x   = (const float*)d_in[0];
    const void*  seg = d_in[1];
    float* out = (float*)d_out;

    const int D = 128;
    const int n = in_sizes[0] / D;          // number of rows
    const int G = out_size / (4 * D);       // number of segments

    int tb = 256;
    int nb = (n + tb - 1) / tb;
    seg_boundaries_kernel<<<nb, tb>>>(seg, n, G);
    seg_pool_kernel<<<G, 128>>>(x, out, G);
}